// round 16
// baseline (speedup 1.0000x reference)
#include <cuda_runtime.h>
#include <cstdint>

// STN bilinear sampler, v16 — 256-bit global accesses (sm_100+ v8.f32).
// x: [32,256,256,32] f32 NHWC ; theta: [32,6] f32 ; out: same shape.
// 4 threads/pixel, 32B (8 floats) each: a warp's gather instruction touches
// 8 distinct 128B lines, each fully consumed in ONE wavefront (same per-byte
// L1 cost as the best 128-bit layout) while halving LDG/STG instruction count
// and halving coordinate-math replication. 8 rows/thread.

#define B_ 32
#define H_ 256
#define W_ 256
#define ROWS_ 8
#define STEP (2.0f / 255.0f)

struct F8 { float v[8]; };

__device__ __forceinline__ F8 ldg256(const float* p) {
    F8 r;
    asm volatile("ld.global.nc.v8.f32 {%0,%1,%2,%3,%4,%5,%6,%7}, [%8];"
                 : "=f"(r.v[0]), "=f"(r.v[1]), "=f"(r.v[2]), "=f"(r.v[3]),
                   "=f"(r.v[4]), "=f"(r.v[5]), "=f"(r.v[6]), "=f"(r.v[7])
                 : "l"(p));
    return r;
}

__device__ __forceinline__ void stg256_cs(float* p, const F8& r) {
    asm volatile("st.global.cs.v8.f32 [%0], {%1,%2,%3,%4,%5,%6,%7,%8};"
                 :: "l"(p),
                    "f"(r.v[0]), "f"(r.v[1]), "f"(r.v[2]), "f"(r.v[3]),
                    "f"(r.v[4]), "f"(r.v[5]), "f"(r.v[6]), "f"(r.v[7])
                 : "memory");
}

__global__ __launch_bounds__(256) void stn_kernel(
    const float* __restrict__ x,
    const float* __restrict__ theta,
    float* __restrict__ out)
{
    int gid = blockIdx.x * blockDim.x + threadIdx.x;   // [0, 2^20)
    int h   = gid & 3;                 // 32B chunk within pixel (8 floats)
    int ox  = (gid >> 2) & 255;
    int oy8 = (gid >> 10) & 31;        // 8-row group index
    int b   = gid >> 15;               // batch
    int oy  = oy8 << 3;
    int co  = h << 3;                  // float offset within pixel (0..24)

    // theta via 3x LDG.64 (8B-aligned: b*24 bytes), uniform per batch
    const float2* t2p = (const float2*)(theta + b * 6);
    float2 q0 = __ldg(t2p + 0);
    float2 q1 = __ldg(t2p + 1);
    float2 q2 = __ldg(t2p + 2);
    float t0 = q0.x, t1 = q0.y, t2 = q1.x;
    float t3 = q1.y, t4 = q2.x, t5 = q2.y;

    float gx = -1.0f + (float)ox * STEP;
    int basep = b << 16;               // b * H*W (pixel units)
    int obase = ((basep + (oy << 8) + ox) << 5) + co;   // float units

#pragma unroll
    for (int k = 0; k < ROWS_; k++) {
        float gy = -1.0f + (float)(oy + k) * STEP;

        // identical formula to reference: 0.5*(T·g + 1)*N, truncate toward zero
        float sx = 0.5f * (t0 * gx + t1 * gy + t2 + 1.0f) * (float)W_;
        float sy = 0.5f * (t3 * gx + t4 * gy + t5 + 1.0f) * (float)H_;

        int x0 = (int)sx;
        int y0 = (int)sy;

        int x0c = min(max(x0, 0), W_ - 1);
        int x1c = min(max(x0 + 1, 0), W_ - 1);
        int y0c = min(max(y0, 0), H_ - 1);
        int y1c = min(max(y0 + 1, 0), H_ - 1);

        float x0f = (float)x0c, x1f = (float)x1c;
        float y0f = (float)y0c, y1f = (float)y1c;

        float wa = (x1f - sx) * (y1f - sy);
        float wb = (x1f - sx) * (sy - y0f);
        float wc = (sx - x0f) * (y1f - sy);
        float wd = (sx - x0f) * (sy - y0f);

        // float-unit indices; x1 column derived via dx (0 or 32)
        int dx = (x1c - x0c) << 5;
        int ia = ((basep + (y0c << 8) + x0c) << 5) + co;
        int ib = ((basep + (y1c << 8) + x0c) << 5) + co;

        // 4 LDG.256 per row (vs 8 LDG.128 for the same bytes at 32B/thread)
        F8 pa = ldg256(x + ia);
        F8 pc = ldg256(x + ia + dx);
        F8 pb = ldg256(x + ib);
        F8 pd = ldg256(x + ib + dx);

        F8 o;
#pragma unroll
        for (int i = 0; i < 8; i++)
            o.v[i] = wa * pa.v[i] + wb * pb.v[i]
                   + wc * pc.v[i] + wd * pd.v[i];

        // one streaming STG.256 (output write-once, keep L2 for gathers)
        stg256_cs(out + obase + (k << 13), o);   // + k * W_ * 32 floats
    }
}

extern "C" void kernel_launch(void* const* d_in, const int* in_sizes, int n_in,
                              void* d_out, int out_size)
{
    const float* x     = (const float*)d_in[0];
    const float* theta = (const float*)d_in[1];
    float* out = (float*)d_out;

    int total_threads = B_ * (H_ / ROWS_) * W_ * 4;   // 1,048,576
    int block = 256;
    int grid = total_threads / block;                  // 4,096
    stn_kernel<<<grid, block>>>(x, theta, out);
}